// round 15
// baseline (speedup 1.0000x reference)
#include <cuda_runtime.h>
#include <cuda_bf16.h>
#include <math.h>
#include <stdint.h>

#define D_MODEL 1024
#define NHEAD   16
#define HEAD_DIM 64
#define B_SZ    4
#define L_SEQ   4096
#define M_ROWS  (B_SZ * L_SEQ)       // 16384
#define CHUNK   128
#define NCHUNK  (L_SEQ / CHUNK)      // 32
#define LN_EPS  1e-5f

// GEMM tiling: 128x128 CTA tile, 256 threads (8 warps, 2x4, 64x32 each)
// Stage: A(16KB) | Bhi(16KB) | Blo(16KB); 2 stages; 2 CTAs/SM.
#define TM 128
#define TN 128
#define TK 64
#define STAGE_BYTES 49152
#define A_OFF  0
#define BH_OFF 16384
#define BL_OFF 32768
#define NKT2 32
#define GEMM_SMEM_SZ (2 * STAGE_BYTES)   // 98304

#define NW (D_MODEL * D_MODEL)
#define WSEG (2u * (unsigned)NW)

// ---------------- scratch (device globals) -----------------------------------
__device__ __nv_bfloat16 g_xs[2u * M_ROWS * D_MODEL];
__device__ __nv_bfloat16 g_ys[2u * M_ROWS * D_MODEL];
__device__ __nv_bfloat16 g_ws[4u * 2u * D_MODEL * D_MODEL];
__device__ float g_q[M_ROWS * D_MODEL];
__device__ float g_v[M_ROWS * D_MODEL];
__device__ float g_g[M_ROWS * D_MODEL];
__device__ float g_carry[B_SZ * NHEAD * NCHUNK * HEAD_DIM];
__device__ float g_P[B_SZ * NHEAD * NCHUNK * HEAD_DIM];
__device__ float g_lampow[CHUNK * NHEAD];   // lam[h]^(j+1), layout [j][h]

// ---------------- PTX helpers ------------------------------------------------
#define CP16(dst, src) \
    asm volatile("cp.async.cg.shared.global [%0], [%1], 16;" :: "r"(dst), "l"(src))
#define CP_COMMIT() asm volatile("cp.async.commit_group;" ::: "memory")
#define CP_WAIT0()  asm volatile("cp.async.wait_group 0;" ::: "memory")

#define LDSM4(r0, r1, r2, r3, addr) \
    asm volatile("ldmatrix.sync.aligned.m8n8.x4.shared.b16 {%0,%1,%2,%3}, [%4];" \
        : "=r"(r0), "=r"(r1), "=r"(r2), "=r"(r3) : "r"(addr))

#define MMA16816(d, a, b0, b1) \
    asm volatile("mma.sync.aligned.m16n8k16.row.col.f32.bf16.bf16.f32 " \
        "{%0,%1,%2,%3}, {%4,%5,%6,%7}, {%8,%9}, {%0,%1,%2,%3};" \
        : "+f"((d)[0]), "+f"((d)[1]), "+f"((d)[2]), "+f"((d)[3]) \
        : "r"((a)[0]), "r"((a)[1]), "r"((a)[2]), "r"((a)[3]), "r"(b0), "r"(b1))

__device__ __forceinline__ uint32_t swz(uint32_t off) {
    return off ^ ((off >> 3) & 0x70);
}

// ---------------- split fp32 -> bf16 hi/lo -----------------------------------
__device__ __forceinline__ void split4(const float* __restrict__ in,
                                       __nv_bfloat16* __restrict__ out,
                                       int i, int n)
{
    float4 v = *(const float4*)(in + i);
    __nv_bfloat16 h0 = __float2bfloat16_rn(v.x);
    __nv_bfloat16 h1 = __float2bfloat16_rn(v.y);
    __nv_bfloat16 h2 = __float2bfloat16_rn(v.z);
    __nv_bfloat16 h3 = __float2bfloat16_rn(v.w);
    __nv_bfloat16 l0 = __float2bfloat16_rn(v.x - __bfloat162float(h0));
    __nv_bfloat16 l1 = __float2bfloat16_rn(v.y - __bfloat162float(h1));
    __nv_bfloat16 l2 = __float2bfloat16_rn(v.z - __bfloat162float(h2));
    __nv_bfloat16 l3 = __float2bfloat16_rn(v.w - __bfloat162float(h3));
    __nv_bfloat162* oh = (__nv_bfloat162*)(out + i);
    oh[0] = __nv_bfloat162(h0, h1); oh[1] = __nv_bfloat162(h2, h3);
    __nv_bfloat162* ol = (__nv_bfloat162*)(out + n + i);
    ol[0] = __nv_bfloat162(l0, l1); ol[1] = __nv_bfloat162(l2, l3);
}

// one launch covers x (blocks 0..16383) and all 4 weights (blocks 16384..20479)
__global__ __launch_bounds__(256) void split_all(
    const float* __restrict__ x,
    const float* __restrict__ w0, const float* __restrict__ w1,
    const float* __restrict__ w2, const float* __restrict__ w3)
{
    const int blk = blockIdx.x;
    if (blk < M_ROWS * D_MODEL / 1024) {
        int i = (blk * 256 + threadIdx.x) * 4;
        split4(x, g_xs, i, M_ROWS * D_MODEL);
    } else {
        int wb = blk - M_ROWS * D_MODEL / 1024;
        int wi = wb >> 10;                       // 0..3
        const float* src = (wi == 0) ? w0 : (wi == 1) ? w1 : (wi == 2) ? w2 : w3;
        int i = ((wb & 1023) * 256 + threadIdx.x) * 4;
        split4(src, g_ws + (size_t)wi * WSEG, i, NW);
    }
}

// ---------------- core GEMM tile machinery ------------------------------------
__device__ __forceinline__ void load_tile(
    const __nv_bfloat16* __restrict__ A, const __nv_bfloat16* __restrict__ B,
    int bm, int bn, int kt, uint32_t stg, int tid)
{
    const bool dual = (kt < 16);
    const int kl = dual ? kt : (kt - 16);
    const size_t kcol = (size_t)kl * TK;
    const size_t arow0 = (size_t)bm + (dual ? 0 : (size_t)M_ROWS);
#pragma unroll
    for (int i = 0; i < 12; i++) {
        if (i >= 8 && !dual) continue;
        int c = tid + i * 256;                  // 0..3071
        int part = c >> 10;                     // 0=A, 1=Bhi, 2=Blo
        int row = (c >> 3) & 127;
        int seg = c & 7;
        const __nv_bfloat16* src;
        if (part == 0)      src = A + (arow0 + row) * D_MODEL + kcol + seg * 8;
        else if (part == 1) src = B + (size_t)(bn + row) * D_MODEL + kcol + seg * 8;
        else                src = B + (size_t)(D_MODEL + bn + row) * D_MODEL + kcol + seg * 8;
        uint32_t off = (uint32_t)(row * 128 + seg * 16);
        uint32_t dst = stg + (uint32_t)(part * 16384) + swz(off);
        CP16(dst, src);
    }
}

// full GEMM body for one 128x128 tile; A/B are hi-base pointers. 256 threads.
// SCANV: fuse per-chunk retention scan into the epilogue (C == g_v path).
template <bool SCANV>
__device__ __forceinline__ void gemm_tile_body(
    const __nv_bfloat16* __restrict__ A, const __nv_bfloat16* __restrict__ B,
    float* __restrict__ C, int bm, int bn, uint32_t sbase, char* smem_gen,
    int tid, const float* __restrict__ beta)
{
    const int wid = tid >> 5;
    const int lane = tid & 31;
    const int wm = (wid >> 2) * 64;   // 0 or 64
    const int wn = (wid & 3) * 32;    // 0,32,64,96

    float acc[4][4][4];
#pragma unroll
    for (int i = 0; i < 4; i++)
#pragma unroll
        for (int j = 0; j < 4; j++)
#pragma unroll
            for (int r = 0; r < 4; r++) acc[i][j][r] = 0.f;

    load_tile(A, B, bm, bn, 0, sbase, tid); CP_COMMIT();

    const int lrow = lane & 15;
    const int lcol = (lane >> 4) << 4;

    for (int kt = 0; kt < NKT2; kt++) {
        const uint32_t sa = sbase + (kt & 1) * STAGE_BYTES;
        const bool dual = (kt < 16);

        CP_WAIT0();
        __syncthreads();

        if (kt + 1 < NKT2)
            load_tile(A, B, bm, bn, kt + 1, sbase + ((kt + 1) & 1) * STAGE_BYTES, tid);
        CP_COMMIT();

#pragma unroll
        for (int kk = 0; kk < 4; kk++) {
            const uint32_t colb = (uint32_t)(kk * 32 + lcol);
            uint32_t a[4][4];
#pragma unroll
            for (int mi = 0; mi < 4; mi++) {
                uint32_t off = (uint32_t)((wm + mi * 16 + lrow) * 128) + colb;
                LDSM4(a[mi][0], a[mi][1], a[mi][2], a[mi][3], sa + A_OFF + swz(off));
            }
            uint32_t bh[2][4];
#pragma unroll
            for (int j2 = 0; j2 < 2; j2++) {
                uint32_t off = (uint32_t)((wn + j2 * 16 + lrow) * 128) + colb;
                LDSM4(bh[j2][0], bh[j2][1], bh[j2][2], bh[j2][3], sa + BH_OFF + swz(off));
            }
#pragma unroll
            for (int mi = 0; mi < 4; mi++)
#pragma unroll
                for (int j = 0; j < 4; j++) {
                    const int j2 = j >> 1, jj = j & 1;
                    MMA16816(acc[mi][j], a[mi], bh[j2][jj], bh[j2][2 + jj]);
                }
            if (dual) {
                uint32_t bl[2][4];
#pragma unroll
                for (int j2 = 0; j2 < 2; j2++) {
                    uint32_t off = (uint32_t)((wn + j2 * 16 + lrow) * 128) + colb;
                    LDSM4(bl[j2][0], bl[j2][1], bl[j2][2], bl[j2][3], sa + BL_OFF + swz(off));
                }
#pragma unroll
                for (int mi = 0; mi < 4; mi++)
#pragma unroll
                    for (int j = 0; j < 4; j++) {
                        const int j2 = j >> 1, jj = j & 1;
                        MMA16816(acc[mi][j], a[mi], bl[j2][jj], bl[j2][2 + jj]);
                    }
            }
        }
    }

    const int r0 = lane >> 2;
    const int c0 = (lane & 3) * 2;

    if (!SCANV) {
#pragma unroll
        for (int mi = 0; mi < 4; mi++) {
#pragma unroll
            for (int j = 0; j < 4; j++) {
                float* cp0 = C + (size_t)(bm + wm + mi * 16 + r0) * D_MODEL + bn + wn + j * 8 + c0;
                float* cp1 = cp0 + 8 * D_MODEL;
                *(float2*)cp0 = make_float2(acc[mi][j][0], acc[mi][j][1]);
                *(float2*)cp1 = make_float2(acc[mi][j][2], acc[mi][j][3]);
            }
        }
    } else {
        // fused per-chunk retention scan. this CTA covers one 128-token chunk
        // (rows bm..bm+127) x 128 dims (cols bn..bn+127).
        float* sf = (float*)smem_gen;     // 128 x 128 f32 = 64KB (stages are dead)
        __syncthreads();                  // all warps done reading stage smem
#pragma unroll
        for (int mi = 0; mi < 4; mi++) {
#pragma unroll
            for (int j = 0; j < 4; j++) {
                int srow = wm + mi * 16 + r0;
                int scol = wn + j * 8 + c0;
                *(float2*)(sf + srow * 128 + scol) = make_float2(acc[mi][j][0], acc[mi][j][1]);
                *(float2*)(sf + (srow + 8) * 128 + scol) = make_float2(acc[mi][j][2], acc[mi][j][3]);
            }
        }
        __syncthreads();

        const int b = bm / L_SEQ;
        const int c = (bm % L_SEQ) / CHUNK;
        if (tid < 128) {
            const int gcol = bn + tid;
            const int h = gcol >> 6;
            const int dh = gcol & 63;
            const float lam = 1.f / (1.f + expf(-beta[h]));
            float s = 0.f;
#pragma unroll 4
            for (int t = 0; t < CHUNK; t++) {
                s = fmaf(lam, s, sf[t * 128 + tid]);
                sf[t * 128 + tid] = s;
            }
            g_carry[((b * NHEAD + h) * NCHUNK + c) * HEAD_DIM + dh] = s;
        }
        __syncthreads();

        // coalesced write-out of scanned v
#pragma unroll
        for (int idx = tid; idx < 128 * 32; idx += 256) {
            int row = idx >> 5;
            int c4 = (idx & 31) * 4;
            float4 vv = *(float4*)(sf + row * 128 + c4);
            *(float4*)(C + (size_t)(bm + row) * D_MODEL + bn + c4) = vv;
        }
    }
}

// merged q/v/g projection GEMM: grid.x in [0,24) covers 3 weight segments
__global__ __launch_bounds__(256, 2)
void gemm_qvg(const float* __restrict__ beta)
{
    extern __shared__ char smem[];
    const uint32_t sbase = (uint32_t)__cvta_generic_to_shared(smem);
    const int tid = threadIdx.x;
    const int bng = blockIdx.x * TN;          // 0..3071
    const int seg = bng >> 10;
    const int bn = bng & 1023;
    const int bm = blockIdx.y * TM;

    const __nv_bfloat16* B = g_ws + (size_t)seg * WSEG;

    if (seg == 1) {
        gemm_tile_body<true>(g_xs, B, g_v, bm, bn, sbase, smem, tid, beta);
    } else {
        float* C = (seg == 0) ? g_q : g_g;
        gemm_tile_body<false>(g_xs, B, C, bm, bn, sbase, smem, tid, beta);
    }
}

__global__ __launch_bounds__(256, 2)
void gemm_out(float* __restrict__ C)
{
    extern __shared__ char smem[];
    const uint32_t sbase = (uint32_t)__cvta_generic_to_shared(smem);
    gemm_tile_body<false>(g_ys, g_ws + 3 * (size_t)WSEG, C,
                          blockIdx.y * TM, blockIdx.x * TN, sbase, smem,
                          threadIdx.x, nullptr);
}

// ---------------- carry prefix across chunks (MLP-prefetched) ------------------
// also fills the lam^(j+1) table used by ln_gate
__global__ void scan_prefix(const float* __restrict__ beta)
{
    int idx = blockIdx.x * blockDim.x + threadIdx.x;
    if (idx >= B_SZ * NHEAD * HEAD_DIM) return;

    // lam power table: [j][h], 2048 entries (first 2048 threads)
    if (idx < CHUNK * NHEAD) {
        int h = idx & (NHEAD - 1);
        int j = idx >> 4;
        float lam = 1.f / (1.f + expf(-beta[h]));
        g_lampow[idx] = powf(lam, (float)(j + 1));
    }

    const int dh = idx % HEAD_DIM;
    const int h = (idx / HEAD_DIM) % NHEAD;
    const int b = idx / (HEAD_DIM * NHEAD);

    const float lam = 1.f / (1.f + expf(-beta[h]));
    const float lamC = powf(lam, (float)CHUNK);

    const int base = (b * NHEAD + h) * NCHUNK * HEAD_DIM + dh;

    // independent loads first: full MLP, one memory latency total
    float carr[NCHUNK];
#pragma unroll
    for (int c = 0; c < NCHUNK; c++)
        carr[c] = g_carry[base + c * HEAD_DIM];

    float P = 0.f;
#pragma unroll
    for (int c = 0; c < NCHUNK; c++) {
        g_P[base + c * HEAD_DIM] = P;
        P = fmaf(lamC, P, carr[c]);
    }
}

// ---------------- fused: y = LN(q*state)*silu(gate) -> bf16 hi/lo --------------
// one WARP per token: 32 lanes x 8 float4 = 1024 dims. no barriers, no smem.
__global__ __launch_bounds__(256) void ln_gate_kernel(
    const float* __restrict__ gamma,
    const float* __restrict__ lnb)
{
    const int lane = threadIdx.x & 31;
    const int token = blockIdx.x * 8 + (threadIdx.x >> 5);
    const int b = token / L_SEQ;
    const int t = token % L_SEQ;
    const int c = t / CHUNK;
    const int j = t % CHUNK;

    const size_t o0 = (size_t)token * D_MODEL + lane * 4;
    const int pbase = ((b * NHEAD) * NCHUNK + c) * HEAD_DIM;   // head 0 base
    const int pdh = (lane * 4) & 63;                           // dh within head
    const int hlo = lane >> 4;                                 // 0 or 1 (head parity)

    // phase 1: load q, v, P; compute z; accumulate stats
    float z[32];
    float lsum = 0.f, lsq = 0.f;
#pragma unroll
    for (int i = 0; i < 8; i++) {
        const int h = i * 2 + hlo;
        const float lj = g_lampow[j * NHEAD + h];
        float4 qv = *(const float4*)(g_q + o0 + i * 128);
        float4 vv = *(const float4*)(g_v + o0 + i * 128);
        float4 Pv = *(const float4*)(g_P + pbase + h * NCHUNK * HEAD_DIM + pdh);
        float z0 = qv.x * fmaf(lj, Pv.x, vv.x);
        float z1 = qv.y * fmaf(lj, Pv.y, vv.y);
        float z2 = qv.z * fmaf(lj, Pv.z, vv.z);
        float z3 = qv.w * fmaf(lj, Pv.w, vv.w);
        z[i * 4 + 0] = z0; z[i * 4 + 1] = z1; z[i * 4 + 2] = z2; z[i * 4 + 3] = z3;
        lsum += z0 + z1 + z2 + z3;
        lsq = fmaf(z0, z0, fmaf(z1, z1, fmaf(z2, z2, fmaf(z3, z3, lsq))));
    }

    // warp-only reduction (deterministic)
#pragma unroll
    for (int off = 16; off; off >>= 1) {
        lsum += __shfl_xor_sync(0xffffffffu, lsum, off);
        lsq  += __shfl_xor_sync(0xffffffffu, lsq, off);
    }

    const float inv = 1.f / (float)D_MODEL;
    const float mu = lsum * inv;
    const float var = lsq * inv - mu * mu;
    const float r = rsqrtf(var + LN_EPS);

    // phase 2: gamma/lnb/gate, write bf16 hi/lo
    const size_t olo = o0 + (size_t)M_ROWS * D_MODEL;
#pragma unroll
    for (int i = 0; i < 8; i++) {
        float4 gam = *(const float4*)(gamma + lane * 4 + i * 128);
        float4 lnbv = *(const float4*)(lnb + lane * 4 + i * 128);
        float4 gv = *(const float4*)(g_g + o0 + i * 128);
        float y0 = (z[i * 4 + 0] - mu) * r * gam.x + lnbv.x;
        float y1 = (z[i * 4 + 1] - mu) * r * gam.y + lnbv.y;
        float y2 = (z[i * 4 + 2] - mu) * r * gam.z + lnbv.z;
        float y3 = (z[i * 4 + 3] - mu) * r * gam.w + lnbv.w;
        y0 *= __fdividef(gv.x, 1.f + __expf(-gv.x));
        y1 *= __fdividef(gv.y, 1.f + __expf(-gv.y));
        y2 *= __fdividef(gv.z, 1.f + __expf(-gv.z));
        y3 *= __fdividef(gv.w, 1.f + __expf(-gv.w));

        __nv_bfloat16 h0 = __float2bfloat16_rn(y0);
        __nv_bfloat16 h1 = __float2bfloat16_rn(y1);
        __nv_bfloat16 h2 = __float2bfloat16_rn(y2);
        __nv_bfloat16 h3 = __float2bfloat16_rn(y3);
        *(__nv_bfloat162*)(g_ys + o0 + i * 128) = __nv_bfloat162(h0, h1);
        *(__nv_bfloat162*)(g_ys + o0 + i * 128 + 2) = __nv_bfloat162(h2, h3);

        __nv_bfloat16 l0 = __float2bfloat16_rn(y0 - __bfloat162float(h0));
        __nv_bfloat16 l1 = __float2bfloat16_rn(y1 - __bfloat162float(h1));
        __nv_bfloat16 l2 = __float2bfloat16_rn(y2 - __bfloat162float(h2));
        __nv_bfloat16 l3 = __float2bfloat16_rn(y3 - __bfloat162float(h3));
        *(__nv_bfloat162*)(g_ys + olo + i * 128) = __nv_bfloat162(l0, l1);
        *(__nv_bfloat162*)(g_ys + olo + i * 128 + 2) = __nv_bfloat162(l2, l3);
    }
}

// ---------------- launch ------------------------------------------------------
extern "C" void kernel_launch(void* const* d_in, const int* in_sizes, int n_in,
                              void* d_out, int out_size)
{
    const float* x     = (const float*)d_in[0];
    const float* Wq    = (const float*)d_in[1];
    const float* Wv    = (const float*)d_in[2];
    const float* Wg    = (const float*)d_in[3];
    const float* Wo    = (const float*)d_in[4];
    const float* beta  = (const float*)d_in[5];
    const float* gamma = (const float*)d_in[6];
    const float* lnb   = (const float*)d_in[7];
    float* out = (float*)d_out;

    cudaFuncSetAttribute(gemm_qvg, cudaFuncAttributeMaxDynamicSharedMemorySize, GEMM_SMEM_SZ);
    cudaFuncSetAttribute(gemm_out, cudaFuncAttributeMaxDynamicSharedMemorySize, GEMM_SMEM_SZ);

    const int NX = M_ROWS * D_MODEL;
    const int NBLK = NX / 1024 + 4 * (NW / 1024);   // 16384 + 4096

    split_all<<<NBLK, 256>>>(x, Wq, Wv, Wg, Wo);

    gemm_qvg<<<dim3(3 * D_MODEL / TN, M_ROWS / TM), 256, GEMM_SMEM_SZ>>>(beta);  // (24,128)

    scan_prefix<<<(B_SZ * NHEAD * HEAD_DIM + 255) / 256, 256>>>(beta);

    ln_gate_kernel<<<M_ROWS / 8, 256>>>(gamma, lnb);

    gemm_out<<<dim3(D_MODEL / TN, M_ROWS / TM), 256, GEMM_SMEM_SZ>>>(out);       // (8,128)
}

// round 16
// speedup vs baseline: 1.0136x; 1.0136x over previous
#include <cuda_runtime.h>
#include <cuda_bf16.h>
#include <math.h>
#include <stdint.h>

#define D_MODEL 1024
#define NHEAD   16
#define HEAD_DIM 64
#define B_SZ    4
#define L_SEQ   4096
#define M_ROWS  (B_SZ * L_SEQ)       // 16384
#define CHUNK   128
#define NCHUNK  (L_SEQ / CHUNK)      // 32
#define LN_EPS  1e-5f

// GEMM tiling: 128x128 CTA tile, 256 threads (8 warps, 2x4, 64x32 each)
// Stage: A(16KB) | Bhi(16KB) | Blo(16KB); 2 stages; 2 CTAs/SM.
#define TM 128
#define TN 128
#define TK 64
#define STAGE_BYTES 49152
#define A_OFF  0
#define BH_OFF 16384
#define BL_OFF 32768
#define NKT2 32
#define GEMM_SMEM_SZ (2 * STAGE_BYTES)   // 98304

#define NW (D_MODEL * D_MODEL)
#define WSEG (2u * (unsigned)NW)

// ---------------- scratch (device globals) -----------------------------------
__device__ __nv_bfloat16 g_xs[2u * M_ROWS * D_MODEL];
__device__ __nv_bfloat16 g_ys[2u * M_ROWS * D_MODEL];
__device__ __nv_bfloat16 g_ws[4u * 2u * D_MODEL * D_MODEL];
__device__ float g_q[M_ROWS * D_MODEL];
__device__ float g_v[M_ROWS * D_MODEL];
__device__ float g_g[M_ROWS * D_MODEL];
__device__ float g_carry[B_SZ * NHEAD * NCHUNK * HEAD_DIM];
__device__ float g_P[B_SZ * NHEAD * NCHUNK * HEAD_DIM];
__device__ float g_lampow[CHUNK * NHEAD];   // lam[h]^(j+1), layout [j][h]

// ---------------- PTX helpers ------------------------------------------------
#define CP16(dst, src) \
    asm volatile("cp.async.cg.shared.global [%0], [%1], 16;" :: "r"(dst), "l"(src))
#define CP_COMMIT() asm volatile("cp.async.commit_group;" ::: "memory")
#define CP_WAIT0()  asm volatile("cp.async.wait_group 0;" ::: "memory")

#define LDSM4(r0, r1, r2, r3, addr) \
    asm volatile("ldmatrix.sync.aligned.m8n8.x4.shared.b16 {%0,%1,%2,%3}, [%4];" \
        : "=r"(r0), "=r"(r1), "=r"(r2), "=r"(r3) : "r"(addr))

#define MMA16816(d, a, b0, b1) \
    asm volatile("mma.sync.aligned.m16n8k16.row.col.f32.bf16.bf16.f32 " \
        "{%0,%1,%2,%3}, {%4,%5,%6,%7}, {%8,%9}, {%0,%1,%2,%3};" \
        : "+f"((d)[0]), "+f"((d)[1]), "+f"((d)[2]), "+f"((d)[3]) \
        : "r"((a)[0]), "r"((a)[1]), "r"((a)[2]), "r"((a)[3]), "r"(b0), "r"(b1))

__device__ __forceinline__ uint32_t swz(uint32_t off) {
    return off ^ ((off >> 3) & 0x70);
}

__device__ __forceinline__ unsigned pack_bf16(__nv_bfloat16 lo, __nv_bfloat16 hi) {
    return ((unsigned)__bfloat16_as_ushort(hi) << 16) | __bfloat16_as_ushort(lo);
}

// ---------------- split fp32 -> bf16 hi/lo -----------------------------------
__device__ __forceinline__ void split4(const float* __restrict__ in,
                                       __nv_bfloat16* __restrict__ out,
                                       int i, int n)
{
    float4 v = *(const float4*)(in + i);
    __nv_bfloat16 h0 = __float2bfloat16_rn(v.x);
    __nv_bfloat16 h1 = __float2bfloat16_rn(v.y);
    __nv_bfloat16 h2 = __float2bfloat16_rn(v.z);
    __nv_bfloat16 h3 = __float2bfloat16_rn(v.w);
    __nv_bfloat16 l0 = __float2bfloat16_rn(v.x - __bfloat162float(h0));
    __nv_bfloat16 l1 = __float2bfloat16_rn(v.y - __bfloat162float(h1));
    __nv_bfloat16 l2 = __float2bfloat16_rn(v.z - __bfloat162float(h2));
    __nv_bfloat16 l3 = __float2bfloat16_rn(v.w - __bfloat162float(h3));
    __nv_bfloat162* oh = (__nv_bfloat162*)(out + i);
    oh[0] = __nv_bfloat162(h0, h1); oh[1] = __nv_bfloat162(h2, h3);
    __nv_bfloat162* ol = (__nv_bfloat162*)(out + n + i);
    ol[0] = __nv_bfloat162(l0, l1); ol[1] = __nv_bfloat162(l2, l3);
}

// one launch covers x (blocks 0..16383) and all 4 weights (blocks 16384..20479)
__global__ __launch_bounds__(256) void split_all(
    const float* __restrict__ x,
    const float* __restrict__ w0, const float* __restrict__ w1,
    const float* __restrict__ w2, const float* __restrict__ w3)
{
    const int blk = blockIdx.x;
    if (blk < M_ROWS * D_MODEL / 1024) {
        int i = (blk * 256 + threadIdx.x) * 4;
        split4(x, g_xs, i, M_ROWS * D_MODEL);
    } else {
        int wb = blk - M_ROWS * D_MODEL / 1024;
        int wi = wb >> 10;                       // 0..3
        const float* src = (wi == 0) ? w0 : (wi == 1) ? w1 : (wi == 2) ? w2 : w3;
        int i = ((wb & 1023) * 256 + threadIdx.x) * 4;
        split4(src, g_ws + (size_t)wi * WSEG, i, NW);
    }
}

// ---------------- core GEMM tile machinery ------------------------------------
__device__ __forceinline__ void load_tile(
    const __nv_bfloat16* __restrict__ A, const __nv_bfloat16* __restrict__ B,
    int bm, int bn, int kt, uint32_t stg, int tid)
{
    const bool dual = (kt < 16);
    const int kl = dual ? kt : (kt - 16);
    const size_t kcol = (size_t)kl * TK;
    const size_t arow0 = (size_t)bm + (dual ? 0 : (size_t)M_ROWS);
#pragma unroll
    for (int i = 0; i < 12; i++) {
        if (i >= 8 && !dual) continue;
        int c = tid + i * 256;                  // 0..3071
        int part = c >> 10;                     // 0=A, 1=Bhi, 2=Blo
        int row = (c >> 3) & 127;
        int seg = c & 7;
        const __nv_bfloat16* src;
        if (part == 0)      src = A + (arow0 + row) * D_MODEL + kcol + seg * 8;
        else if (part == 1) src = B + (size_t)(bn + row) * D_MODEL + kcol + seg * 8;
        else                src = B + (size_t)(D_MODEL + bn + row) * D_MODEL + kcol + seg * 8;
        uint32_t off = (uint32_t)(row * 128 + seg * 16);
        uint32_t dst = stg + (uint32_t)(part * 16384) + swz(off);
        CP16(dst, src);
    }
}

// full GEMM body for one 128x128 tile; A/B are hi-base pointers. 256 threads.
// SCANV: fuse per-chunk retention scan into the epilogue (C == g_v path).
template <bool SCANV>
__device__ __forceinline__ void gemm_tile_body(
    const __nv_bfloat16* __restrict__ A, const __nv_bfloat16* __restrict__ B,
    float* __restrict__ C, int bm, int bn, uint32_t sbase, char* smem_gen,
    int tid, const float* __restrict__ beta)
{
    const int wid = tid >> 5;
    const int lane = tid & 31;
    const int wm = (wid >> 2) * 64;   // 0 or 64
    const int wn = (wid & 3) * 32;    // 0,32,64,96

    float acc[4][4][4];
#pragma unroll
    for (int i = 0; i < 4; i++)
#pragma unroll
        for (int j = 0; j < 4; j++)
#pragma unroll
            for (int r = 0; r < 4; r++) acc[i][j][r] = 0.f;

    load_tile(A, B, bm, bn, 0, sbase, tid); CP_COMMIT();

    const int lrow = lane & 15;
    const int lcol = (lane >> 4) << 4;

    for (int kt = 0; kt < NKT2; kt++) {
        const uint32_t sa = sbase + (kt & 1) * STAGE_BYTES;
        const bool dual = (kt < 16);

        CP_WAIT0();
        __syncthreads();

        if (kt + 1 < NKT2)
            load_tile(A, B, bm, bn, kt + 1, sbase + ((kt + 1) & 1) * STAGE_BYTES, tid);
        CP_COMMIT();

#pragma unroll
        for (int kk = 0; kk < 4; kk++) {
            const uint32_t colb = (uint32_t)(kk * 32 + lcol);
            uint32_t a[4][4];
#pragma unroll
            for (int mi = 0; mi < 4; mi++) {
                uint32_t off = (uint32_t)((wm + mi * 16 + lrow) * 128) + colb;
                LDSM4(a[mi][0], a[mi][1], a[mi][2], a[mi][3], sa + A_OFF + swz(off));
            }
            uint32_t bh[2][4];
#pragma unroll
            for (int j2 = 0; j2 < 2; j2++) {
                uint32_t off = (uint32_t)((wn + j2 * 16 + lrow) * 128) + colb;
                LDSM4(bh[j2][0], bh[j2][1], bh[j2][2], bh[j2][3], sa + BH_OFF + swz(off));
            }
#pragma unroll
            for (int mi = 0; mi < 4; mi++)
#pragma unroll
                for (int j = 0; j < 4; j++) {
                    const int j2 = j >> 1, jj = j & 1;
                    MMA16816(acc[mi][j], a[mi], bh[j2][jj], bh[j2][2 + jj]);
                }
            if (dual) {
                uint32_t bl[2][4];
#pragma unroll
                for (int j2 = 0; j2 < 2; j2++) {
                    uint32_t off = (uint32_t)((wn + j2 * 16 + lrow) * 128) + colb;
                    LDSM4(bl[j2][0], bl[j2][1], bl[j2][2], bl[j2][3], sa + BL_OFF + swz(off));
                }
#pragma unroll
                for (int mi = 0; mi < 4; mi++)
#pragma unroll
                    for (int j = 0; j < 4; j++) {
                        const int j2 = j >> 1, jj = j & 1;
                        MMA16816(acc[mi][j], a[mi], bl[j2][jj], bl[j2][2 + jj]);
                    }
            }
        }
    }

    const int r0 = lane >> 2;
    const int c0 = (lane & 3) * 2;

    if (!SCANV) {
#pragma unroll
        for (int mi = 0; mi < 4; mi++) {
#pragma unroll
            for (int j = 0; j < 4; j++) {
                float* cp0 = C + (size_t)(bm + wm + mi * 16 + r0) * D_MODEL + bn + wn + j * 8 + c0;
                float* cp1 = cp0 + 8 * D_MODEL;
                *(float2*)cp0 = make_float2(acc[mi][j][0], acc[mi][j][1]);
                *(float2*)cp1 = make_float2(acc[mi][j][2], acc[mi][j][3]);
            }
        }
    } else {
        // fused per-chunk retention scan. this CTA covers one 128-token chunk
        // (rows bm..bm+127) x 128 dims (cols bn..bn+127).
        float* sf = (float*)smem_gen;     // 128 x 128 f32 = 64KB (stages are dead)
        __syncthreads();                  // all warps done reading stage smem
#pragma unroll
        for (int mi = 0; mi < 4; mi++) {
#pragma unroll
            for (int j = 0; j < 4; j++) {
                int srow = wm + mi * 16 + r0;
                int scol = wn + j * 8 + c0;
                *(float2*)(sf + srow * 128 + scol) = make_float2(acc[mi][j][0], acc[mi][j][1]);
                *(float2*)(sf + (srow + 8) * 128 + scol) = make_float2(acc[mi][j][2], acc[mi][j][3]);
            }
        }
        __syncthreads();

        const int b = bm / L_SEQ;
        const int c = (bm % L_SEQ) / CHUNK;
        if (tid < 128) {
            const int gcol = bn + tid;
            const int h = gcol >> 6;
            const int dh = gcol & 63;
            const float lam = 1.f / (1.f + expf(-beta[h]));
            float s = 0.f;
#pragma unroll 4
            for (int t = 0; t < CHUNK; t++) {
                s = fmaf(lam, s, sf[t * 128 + tid]);
                sf[t * 128 + tid] = s;
            }
            g_carry[((b * NHEAD + h) * NCHUNK + c) * HEAD_DIM + dh] = s;
        }
        __syncthreads();

        // coalesced write-out of scanned v
#pragma unroll
        for (int idx = tid; idx < 128 * 32; idx += 256) {
            int row = idx >> 5;
            int c4 = (idx & 31) * 4;
            float4 vv = *(float4*)(sf + row * 128 + c4);
            *(float4*)(C + (size_t)(bm + row) * D_MODEL + bn + c4) = vv;
        }
    }
}

// merged q/v/g projection GEMM: grid.x in [0,24) covers 3 weight segments
__global__ __launch_bounds__(256, 2)
void gemm_qvg(const float* __restrict__ beta)
{
    extern __shared__ char smem[];
    const uint32_t sbase = (uint32_t)__cvta_generic_to_shared(smem);
    const int tid = threadIdx.x;
    const int bng = blockIdx.x * TN;          // 0..3071
    const int seg = bng >> 10;
    const int bn = bng & 1023;
    const int bm = blockIdx.y * TM;

    const __nv_bfloat16* B = g_ws + (size_t)seg * WSEG;

    if (seg == 1) {
        gemm_tile_body<true>(g_xs, B, g_v, bm, bn, sbase, smem, tid, beta);
    } else {
        float* C = (seg == 0) ? g_q : g_g;
        gemm_tile_body<false>(g_xs, B, C, bm, bn, sbase, smem, tid, beta);
    }
}

__global__ __launch_bounds__(256, 2)
void gemm_out(float* __restrict__ C)
{
    extern __shared__ char smem[];
    const uint32_t sbase = (uint32_t)__cvta_generic_to_shared(smem);
    gemm_tile_body<false>(g_ys, g_ws + 3 * (size_t)WSEG, C,
                          blockIdx.y * TM, blockIdx.x * TN, sbase, smem,
                          threadIdx.x, nullptr);
}

// ---------------- carry prefix across chunks (MLP-prefetched) ------------------
// also fills the lam^(j+1) table used by ln_gate
__global__ void scan_prefix(const float* __restrict__ beta)
{
    int idx = blockIdx.x * blockDim.x + threadIdx.x;
    if (idx >= B_SZ * NHEAD * HEAD_DIM) return;

    // lam power table: [j][h], 2048 entries (first 2048 threads)
    if (idx < CHUNK * NHEAD) {
        int h = idx & (NHEAD - 1);
        int j = idx >> 4;
        float lam = 1.f / (1.f + expf(-beta[h]));
        g_lampow[idx] = powf(lam, (float)(j + 1));
    }

    const int dh = idx % HEAD_DIM;
    const int h = (idx / HEAD_DIM) % NHEAD;
    const int b = idx / (HEAD_DIM * NHEAD);

    const float lam = 1.f / (1.f + expf(-beta[h]));
    const float lamC = powf(lam, (float)CHUNK);

    const int base = (b * NHEAD + h) * NCHUNK * HEAD_DIM + dh;

    // independent loads first: full MLP, one memory latency total
    float carr[NCHUNK];
#pragma unroll
    for (int c = 0; c < NCHUNK; c++)
        carr[c] = g_carry[base + c * HEAD_DIM];

    float P = 0.f;
#pragma unroll
    for (int c = 0; c < NCHUNK; c++) {
        g_P[base + c * HEAD_DIM] = P;
        P = fmaf(lamC, P, carr[c]);
    }
}

// ---------------- fused: y = LN(q*state)*silu(gate) -> bf16 hi/lo --------------
// block per token (R14 structure), single barrier, direct lampow loads,
// 8-byte combined bf16 stores.
__global__ __launch_bounds__(256) void ln_gate_kernel(
    const float* __restrict__ gamma,
    const float* __restrict__ lnb)
{
    const int token = blockIdx.x;
    const int b = token / L_SEQ;
    const int t = token % L_SEQ;
    const int c = t / CHUNK;
    const int j = t % CHUNK;
    const int tid = threadIdx.x;
    const int lane = tid & 31;
    const int w = tid >> 5;

    __shared__ float rs[8], rq[8];

    const int d4 = tid * 4;
    const int h = tid >> 4;
    const int dh = d4 & 63;
    const size_t o = (size_t)token * D_MODEL + d4;

    const float lj = g_lampow[j * NHEAD + h];   // direct load, L1-broadcast
    float4 qv = *(const float4*)(g_q + o);
    float4 vv = *(const float4*)(g_v + o);
    float4 gv = *(const float4*)(g_g + o);
    float4 Pv = *(const float4*)(g_P + ((b * NHEAD + h) * NCHUNK + c) * HEAD_DIM + dh);

    float z[4];
    z[0] = qv.x * fmaf(lj, Pv.x, vv.x);
    z[1] = qv.y * fmaf(lj, Pv.y, vv.y);
    z[2] = qv.z * fmaf(lj, Pv.z, vv.z);
    z[3] = qv.w * fmaf(lj, Pv.w, vv.w);

    float lsum = z[0] + z[1] + z[2] + z[3];
    float lsq = fmaf(z[0], z[0], fmaf(z[1], z[1], fmaf(z[2], z[2], z[3] * z[3])));

#pragma unroll
    for (int off = 16; off; off >>= 1) {
        lsum += __shfl_xor_sync(0xffffffffu, lsum, off);
        lsq  += __shfl_xor_sync(0xffffffffu, lsq, off);
    }
    if (lane == 0) { rs[w] = lsum; rq[w] = lsq; }
    __syncthreads();

    // every thread sums the 8 partials itself (deterministic order)
    float s = 0.f, s2 = 0.f;
#pragma unroll
    for (int i = 0; i < 8; i++) { s += rs[i]; s2 += rq[i]; }

    const float inv = 1.f / (float)D_MODEL;
    float mu = s * inv;
    float var = s2 * inv - mu * mu;
    float r = rsqrtf(var + LN_EPS);

    float4 gam = *(const float4*)(gamma + d4);
    float4 lnbv = *(const float4*)(lnb + d4);
    float y0 = (z[0] - mu) * r * gam.x + lnbv.x;
    float y1 = (z[1] - mu) * r * gam.y + lnbv.y;
    float y2 = (z[2] - mu) * r * gam.z + lnbv.z;
    float y3 = (z[3] - mu) * r * gam.w + lnbv.w;
    y0 *= __fdividef(gv.x, 1.f + __expf(-gv.x));
    y1 *= __fdividef(gv.y, 1.f + __expf(-gv.y));
    y2 *= __fdividef(gv.z, 1.f + __expf(-gv.z));
    y3 *= __fdividef(gv.w, 1.f + __expf(-gv.w));

    __nv_bfloat16 h0 = __float2bfloat16_rn(y0);
    __nv_bfloat16 h1 = __float2bfloat16_rn(y1);
    __nv_bfloat16 h2 = __float2bfloat16_rn(y2);
    __nv_bfloat16 h3 = __float2bfloat16_rn(y3);
    *(uint2*)(g_ys + o) = make_uint2(pack_bf16(h0, h1), pack_bf16(h2, h3));

    __nv_bfloat16 l0 = __float2bfloat16_rn(y0 - __bfloat162float(h0));
    __nv_bfloat16 l1 = __float2bfloat16_rn(y1 - __bfloat162float(h1));
    __nv_bfloat16 l2 = __float2bfloat16_rn(y2 - __bfloat162float(h2));
    __nv_bfloat16 l3 = __float2bfloat16_rn(y3 - __bfloat162float(h3));
    const size_t ol = o + (size_t)M_ROWS * D_MODEL;
    *(uint2*)(g_ys + ol) = make_uint2(pack_bf16(l0, l1), pack_bf16(l2, l3));
}

// ---------------- launch ------------------------------------------------------
extern "C" void kernel_launch(void* const* d_in, const int* in_sizes, int n_in,
                              void* d_out, int out_size)
{
    const float* x     = (const float*)d_in[0];
    const float* Wq    = (const float*)d_in[1];
    const float* Wv    = (const float*)d_in[2];
    const float* Wg    = (const float*)d_in[3];
    const float* Wo    = (const float*)d_in[4];
    const float* beta  = (const float*)d_in[5];
    const float* gamma = (const float*)d_in[6];
    const float* lnb   = (const float*)d_in[7];
    float* out = (float*)d_out;

    cudaFuncSetAttribute(gemm_qvg, cudaFuncAttributeMaxDynamicSharedMemorySize, GEMM_SMEM_SZ);
    cudaFuncSetAttribute(gemm_out, cudaFuncAttributeMaxDynamicSharedMemorySize, GEMM_SMEM_SZ);

    const int NX = M_ROWS * D_MODEL;
    const int NBLK = NX / 1024 + 4 * (NW / 1024);   // 16384 + 4096

    split_all<<<NBLK, 256>>>(x, Wq, Wv, Wg, Wo);

    gemm_qvg<<<dim3(3 * D_MODEL / TN, M_ROWS / TM), 256, GEMM_SMEM_SZ>>>(beta);  // (24,128)

    scan_prefix<<<(B_SZ * NHEAD * HEAD_DIM + 255) / 256, 256>>>(beta);

    ln_gate_kernel<<<M_ROWS, 256>>>(gamma, lnb);

    gemm_out<<<dim3(D_MODEL / TN, M_ROWS / TM), 256, GEMM_SMEM_SZ>>>(out);       // (8,128)
}